// round 7
// baseline (speedup 1.0000x reference)
#include <cuda_runtime.h>
#include <cuda_bf16.h>
#include <cstdint>

// ---------------------------------------------------------------------------
// Problem constants
// ---------------------------------------------------------------------------
#define BATCH  256
#define LIN    2048
#define HNODE  256
#define GLEN   24
#define LOUT   2025
#define TWOH   512
#define KDIM   96
#define NTLOC  8             // tiles of 128 l-positions per CTA (l-half)
#define NLOC   1056          // staged local positions (1024 + 23 + pad)
#define NQ     2096          // XiQ slots: 2*1048

// ---------------------------------------------------------------------------
// Shared memory layout (bytes)
// ---------------------------------------------------------------------------
#define OFF_XIQ  0                       // 2096 * 16 = 33536
#define OFF_TH   33536                   // 1056 * 8  = 8448
#define OFF_TL   41984                   // 8448 -> 50432
#define OFF_RED  33536                   // overlay (TH dead): 512 floats
#define SMEM_BYTES 50432

__device__ float g_pp[BATCH * 2 * TWOH];  // per (b, l-half): [max | unscaled sum]
__device__ float g_part[BATCH * 2];       // per (batch, o-half) head partials

// ---------------------------------------------------------------------------
// Helpers
// ---------------------------------------------------------------------------
static __device__ __forceinline__ void bsplit(float v, unsigned short& hi,
                                              unsigned short& lo) {
    __nv_bfloat16 h = __float2bfloat16(v);
    __nv_bfloat16 l = __float2bfloat16(v - __bfloat162float(h));
    hi = __bfloat16_as_ushort(h);
    lo = __bfloat16_as_ushort(l);
}

static __device__ __forceinline__ void mma_bf16(float* d, const uint32_t* a,
                                                uint32_t b0, uint32_t b1) {
    asm volatile(
        "mma.sync.aligned.m16n8k16.row.col.f32.bf16.bf16.f32 "
        "{%0,%1,%2,%3}, {%4,%5,%6,%7}, {%8,%9}, {%0,%1,%2,%3};"
        : "+f"(d[0]), "+f"(d[1]), "+f"(d[2]), "+f"(d[3])
        : "r"(a[0]), "r"(a[1]), "r"(a[2]), "r"(a[3]), "r"(b0), "r"(b1));
}

// ---------------------------------------------------------------------------
// Kernel 1: implicit-GEMM conv, 3-term bf16 split, packed 16B b-fragments.
// Grid: 1024 CTAs = (batch, h-half, l-half). 512 threads = 16 warps,
// warp grid 8(M) x 2(N); warp tile 16(h) x 64(l).
// Inner loop: 8-deep accumulator interleave — same-acc HMMAs are 8 issue
// slots apart (64 cyc), fully covering HMMA latency within a single warp.
// ---------------------------------------------------------------------------
__global__ void __launch_bounds__(512, 1)
conv_mma_kernel(const float* __restrict__ x, const float* __restrict__ wConv,
                const float* __restrict__ wRect) {
    extern __shared__ char smem[];
    const int tid   = threadIdx.x;
    const int lane  = tid & 31;
    const int wid   = tid >> 5;
    const int b     = blockIdx.x >> 2;
    const int mh    = (blockIdx.x >> 1) & 1;
    const int lq    = blockIdx.x & 1;
    const int hbase = mh * 128;
    const int L0    = lq * 1024;
    const int wm    = wid & 7;         // warp M index (0..7), 16 rows each
    const int wn    = wid >> 3;        // warp N index (0..1)
    const int grp   = lane >> 2;       // 0..7
    const int tg    = lane & 3;        // 0..3
    const int kq    = tg * 2;

    unsigned long long* TH = (unsigned long long*)(smem + OFF_TH);
    unsigned long long* TL = (unsigned long long*)(smem + OFF_TL);

    // ---- phase 1: stage local x slice, interleaved bf16x4 hi/lo ----
    const float* xb = x + (size_t)b * 4 * LIN;
    for (int l = tid; l < NLOC; l += 512) {
        const int gl = L0 + l;
        unsigned long long hv = 0ull, lv = 0ull;
        if (gl < LIN) {
            unsigned short h0, l0, h1, l1, h2, l2, h3, l3;
            bsplit(xb[gl],           h0, l0);
            bsplit(xb[LIN + gl],     h1, l1);
            bsplit(xb[2 * LIN + gl], h2, l2);
            bsplit(xb[3 * LIN + gl], h3, l3);
            hv = (unsigned long long)h0 | ((unsigned long long)h1 << 16)
               | ((unsigned long long)h2 << 32) | ((unsigned long long)h3 << 48);
            lv = (unsigned long long)l0 | ((unsigned long long)l1 << 16)
               | ((unsigned long long)l2 << 32) | ((unsigned long long)l3 << 48);
        }
        TH[l] = hv;  TL[l] = lv;
    }
    __syncthreads();

    // ---- phase 2: build packed XiQ. slot(2l+p) = {b0h,b1h,b0l,b1l} ----
    {
        const uint32_t* THw = (const uint32_t*)TH;
        const uint32_t* TLw = (const uint32_t*)TL;
        uint4* XiQ = (uint4*)(smem + OFF_XIQ);
        for (int i = tid; i < NQ; i += 512) {
            uint4 q;
            q.x = THw[i];     q.y = THw[i + 4];
            q.z = TLw[i];     q.w = TLw[i + 4];
            XiQ[i] = q;
        }
    }

    // ---- A fragments straight from gmem (wConv is L2-resident) ----
    uint32_t aH[6][4], aL[6][4];
#pragma unroll
    for (int ks = 0; ks < 6; ++ks)
#pragma unroll
        for (int rr = 0; rr < 4; ++rr) {
            const int r  = wm * 16 + grp + (rr & 1) * 8;
            const int k0 = ks * 16 + kq + (rr >> 1) * 8;      // even
            const int base = (hbase + r) * KDIM + (k0 >> 2);
            const float f0 = wConv[base + (k0 & 3) * GLEN];
            const float f1 = wConv[base + ((k0 & 3) + 1) * GLEN];
            unsigned short h0, lo0, h1, lo1;
            bsplit(f0, h0, lo0);
            bsplit(f1, h1, lo1);
            aH[ks][rr] = (uint32_t)h0  | ((uint32_t)h1  << 16);
            aL[ks][rr] = (uint32_t)lo0 | ((uint32_t)lo1 << 16);
        }

    float rb[2];
    rb[0] = wRect[hbase + wm * 16 + grp];
    rb[1] = wRect[hbase + wm * 16 + 8 + grp];

    __syncthreads();

    const uint4* XiQ = (const uint4*)(smem + OFF_XIQ);
    // slot = 2*(t*128 + wn*64 + nt*8 + grp + 4ks + (tg>>1)) + (tg&1)
    const int sbase = 2 * (wn * 64 + grp + (tg >> 1)) + (tg & 1);

    float mx[2] = {0.f, 0.f};
    float sm[2] = {0.f, 0.f};
    const bool hasMask = (lq == 1);

    for (int t = 0; t < NTLOC; ++t) {
        const int base_t = sbase + 2 * t * 128;

        float d[8][4];
#pragma unroll
        for (int nt = 0; nt < 8; ++nt)
#pragma unroll
            for (int e = 0; e < 4; ++e) d[nt][e] = 0.f;

#pragma unroll
        for (int ks = 0; ks < 6; ++ks) {
            // front-batch the 8 b-fragments for this K step (8 x LDS.128)
            uint4 q[8];
#pragma unroll
            for (int nt = 0; nt < 8; ++nt)
                q[nt] = XiQ[base_t + 2 * (nt * 8 + 4 * ks)];

            // three nt-sweeps: same-accumulator spacing = 8 HMMA slots
#pragma unroll
            for (int nt = 0; nt < 8; ++nt)
                mma_bf16(d[nt], aH[ks], q[nt].x, q[nt].y);
#pragma unroll
            for (int nt = 0; nt < 8; ++nt)
                mma_bf16(d[nt], aH[ks], q[nt].z, q[nt].w);
#pragma unroll
            for (int nt = 0; nt < 8; ++nt)
                mma_bf16(d[nt], aL[ks], q[nt].x, q[nt].y);
        }

        if (!(hasMask && t == NTLOC - 1)) {
#pragma unroll
            for (int nt = 0; nt < 8; ++nt)
#pragma unroll
                for (int e = 0; e < 4; ++e) {
                    const int rh = e >> 1;
                    float r = fmaxf(d[nt][e] + rb[rh], 0.f);
                    mx[rh] = fmaxf(mx[rh], r);
                    sm[rh] += r;
                }
        } else {
            const int lb = L0 + t * 128 + wn * 64;
#pragma unroll
            for (int nt = 0; nt < 8; ++nt)
#pragma unroll
                for (int e = 0; e < 4; ++e) {
                    const int rh = e >> 1;
                    const int n  = lb + nt * 8 + kq + (e & 1);
                    float r = fmaxf(d[nt][e] + rb[rh], 0.f);
                    if (n < LOUT) {
                        mx[rh] = fmaxf(mx[rh], r);
                        sm[rh] += r;
                    }
                }
        }
    }

    // ---- lane-group reduce, cross-wn combine, write partials ----
    __syncthreads();
    float* red = (float*)(smem + OFF_RED);    // 512 floats
#pragma unroll
    for (int rh = 0; rh < 2; ++rh) {
        float mv = mx[rh], sv = sm[rh];
        mv = fmaxf(mv, __shfl_xor_sync(0xffffffffu, mv, 1));
        sv +=        __shfl_xor_sync(0xffffffffu, sv, 1);
        mv = fmaxf(mv, __shfl_xor_sync(0xffffffffu, mv, 2));
        sv +=        __shfl_xor_sync(0xffffffffu, sv, 2);
        if (tg == 0) {
            const int m = wm * 16 + rh * 8 + grp;
            red[wn * 128 + m]       = mv;
            red[256 + wn * 128 + m] = sv;
        }
    }
    __syncthreads();

    if (tid < 128) {
        const float mv = fmaxf(red[tid], red[128 + tid]);
        const float sv = red[256 + tid] + red[384 + tid];
        float* pp = g_pp + (size_t)(b * 2 + lq) * TWOH;
        pp[hbase + tid]         = mv;
        pp[HNODE + hbase + tid] = sv;     // unscaled sum
    }
}

// ---------------------------------------------------------------------------
// Kernel 2: MLP head, batched GEMV with partial-pool combine in staging.
// Grid 128 = (64 batch-quads x 2 o-halves), 256 threads.
// ---------------------------------------------------------------------------
__global__ void __launch_bounds__(256)
mlp_kernel(const float* __restrict__ wH, const float* __restrict__ wHB,
           const float* __restrict__ wNeu) {
    __shared__ float4 prow[TWOH];
    __shared__ float  redsm[32];

    const int tid = threadIdx.x;
    const int bt  = blockIdx.x >> 1;
    const int oh  = blockIdx.x & 1;
    const int o   = oh * 256 + tid;
    const int b0  = bt * 4;

    for (int i = tid; i < TWOH; i += 256) {
        float4 v;
        const float inv = 1.0f / LOUT;
#pragma unroll
        for (int j = 0; j < 4; ++j) {
            const float* p0 = g_pp + (size_t)((b0 + j) * 2 + 0) * TWOH;
            const float* p1 = g_pp + (size_t)((b0 + j) * 2 + 1) * TWOH;
            float val = (i < HNODE) ? fmaxf(p0[i], p1[i])
                                    : (p0[i] + p1[i]) * inv;
            ((float*)&v)[j] = val;
        }
        prow[i] = v;
    }
    __syncthreads();

    float a0 = 0.f, a1 = 0.f, a2 = 0.f, a3 = 0.f;
#pragma unroll 8
    for (int i = 0; i < TWOH; ++i) {
        const float w = wH[i * TWOH + o];
        const float4 p = prow[i];
        a0 = fmaf(p.x, w, a0);
        a1 = fmaf(p.y, w, a1);
        a2 = fmaf(p.z, w, a2);
        a3 = fmaf(p.w, w, a3);
    }

    const float hb = wHB[o];
    const float wv = wNeu[o];
    float vals[4];
    vals[0] = fmaxf(a0 + hb, 0.f) * wv;
    vals[1] = fmaxf(a1 + hb, 0.f) * wv;
    vals[2] = fmaxf(a2 + hb, 0.f) * wv;
    vals[3] = fmaxf(a3 + hb, 0.f) * wv;

    const int lane = tid & 31, wid = tid >> 5;
#pragma unroll
    for (int j = 0; j < 4; ++j) {
        float v = vals[j];
        v += __shfl_xor_sync(0xffffffffu, v, 16);
        v += __shfl_xor_sync(0xffffffffu, v, 8);
        v += __shfl_xor_sync(0xffffffffu, v, 4);
        v += __shfl_xor_sync(0xffffffffu, v, 2);
        v += __shfl_xor_sync(0xffffffffu, v, 1);
        if (lane == 0) redsm[j * 8 + wid] = v;
    }
    __syncthreads();

    if (tid < 32) {
        float v = redsm[tid];
        v += __shfl_xor_sync(0xffffffffu, v, 4);
        v += __shfl_xor_sync(0xffffffffu, v, 2);
        v += __shfl_xor_sync(0xffffffffu, v, 1);
        if ((tid & 7) == 0)
            g_part[(b0 + (tid >> 3)) * 2 + oh] = v;
    }
}

// ---------------------------------------------------------------------------
// Kernel 3: out[b] = 0.5*(p0+p1) + wNeuBias
// ---------------------------------------------------------------------------
__global__ void __launch_bounds__(256)
final_kernel(const float* __restrict__ wNB, float* __restrict__ out) {
    const int b = threadIdx.x;
    out[b] = 0.5f * (g_part[2 * b] + g_part[2 * b + 1]) + wNB[0];
}

// ---------------------------------------------------------------------------
// Launch
// ---------------------------------------------------------------------------
extern "C" void kernel_launch(void* const* d_in, const int* in_sizes, int n_in,
                              void* d_out, int out_size) {
    const float* x     = (const float*)d_in[0];
    const float* wConv = (const float*)d_in[1];
    const float* wRect = (const float*)d_in[2];
    const float* wH    = (const float*)d_in[3];
    const float* wHB   = (const float*)d_in[4];
    const float* wNeu  = (const float*)d_in[5];
    const float* wNB   = (const float*)d_in[6];
    float* out = (float*)d_out;

    static int smem_set = 0;
    if (!smem_set) {
        cudaFuncSetAttribute(conv_mma_kernel,
                             cudaFuncAttributeMaxDynamicSharedMemorySize,
                             SMEM_BYTES);
        smem_set = 1;
    }

    conv_mma_kernel<<<BATCH * 4, 512, SMEM_BYTES>>>(x, wConv, wRect);
    mlp_kernel<<<128, 256>>>(wH, wHB, wNeu);
    final_kernel<<<1, 256>>>(wNB, out);
}

// round 8
// speedup vs baseline: 1.4720x; 1.4720x over previous
#include <cuda_runtime.h>
#include <cuda_fp16.h>
#include <cstdint>

// ---------------------------------------------------------------------------
// Problem constants
// ---------------------------------------------------------------------------
#define BATCH  256
#define LIN    2048
#define HNODE  256
#define GLEN   24
#define LOUT   2025
#define TWOH   512
#define KDIM   96
#define NTLOC  8             // tiles of 128 l-positions per CTA (l-half)
#define NLOC   1056          // staged local positions (1024 + 23 + pad)
#define NQ     2096          // XiQ slots: 2*1048

// ---------------------------------------------------------------------------
// Shared memory layout (bytes)
// ---------------------------------------------------------------------------
#define OFF_XIQ  0                       // 2096 * 16 = 33536
#define OFF_TH   33536                   // 1056 * 8  = 8448
#define OFF_TL   41984                   // 8448 -> 50432
#define OFF_RED  33536                   // overlay (TH dead): 512 floats
#define SMEM_BYTES 50432

__device__ float    g_pp[BATCH * 2 * TWOH];  // per (b, l-half): [max | sum]
__device__ float    g_part[BATCH * 2];       // per (batch, o-half) partials
__device__ uint32_t g_wA[2 * 8 * 32 * 24];   // pre-packed fp16 A-fragments

// ---------------------------------------------------------------------------
// Helpers
// ---------------------------------------------------------------------------
static __device__ __forceinline__ void hsplit(float v, unsigned short& hi,
                                              unsigned short& lo) {
    __half h = __float2half(v);
    __half l = __float2half(v - __half2float(h));
    hi = __half_as_ushort(h);
    lo = __half_as_ushort(l);
}

static __device__ __forceinline__ void mma_f16(float* d, const uint32_t* a,
                                               uint32_t b0, uint32_t b1) {
    asm volatile(
        "mma.sync.aligned.m16n8k16.row.col.f32.f16.f16.f32 "
        "{%0,%1,%2,%3}, {%4,%5,%6,%7}, {%8,%9}, {%0,%1,%2,%3};"
        : "+f"(d[0]), "+f"(d[1]), "+f"(d[2]), "+f"(d[3])
        : "r"(a[0]), "r"(a[1]), "r"(a[2]), "r"(a[3]), "r"(b0), "r"(b1));
}

// ---------------------------------------------------------------------------
// Kernel 0: pre-pack W as fp16 A-fragments, lane-major so each conv thread
// loads its 24 words with 6 LDG.128.  Entry e = ((mh*8+wm)*32+lane)*24 + ks*4+rr
// ---------------------------------------------------------------------------
__global__ void __launch_bounds__(256)
prep_w_kernel(const float* __restrict__ wConv) {
    const int id = blockIdx.x * 256 + threadIdx.x;
    if (id >= 2 * 8 * 32 * 24) return;
    const int mh   = id / 6144;
    const int rem  = id % 6144;
    const int wm   = rem / 768;
    const int rem2 = rem % 768;
    const int lane = rem2 / 24;
    const int j    = rem2 % 24;
    const int ks   = j >> 2;
    const int rr   = j & 3;
    const int grp  = lane >> 2;
    const int tg   = lane & 3;

    const int r  = wm * 16 + grp + (rr & 1) * 8;
    const int k0 = ks * 16 + tg * 2 + (rr >> 1) * 8;          // even
    const int base = (mh * 128 + r) * KDIM + (k0 >> 2);       // k = 4g + c
    const float f0 = wConv[base + (k0 & 3) * GLEN];
    const float f1 = wConv[base + ((k0 & 3) + 1) * GLEN];
    const unsigned short h0 = __half_as_ushort(__float2half(f0));
    const unsigned short h1 = __half_as_ushort(__float2half(f1));
    g_wA[id] = (uint32_t)h0 | ((uint32_t)h1 << 16);
}

// ---------------------------------------------------------------------------
// Kernel 1: implicit-GEMM conv, 2-term fp16 split (W fp16, x = xh + xl),
// packed 16B b-fragments, per-warp tile-order stagger, bias-preloaded
// accumulators. Grid: 1024 CTAs = (batch, h-half, l-half). 512 threads.
// Warp grid 8(M) x 2(N), warp tile 16(h) x 64(l).
// ---------------------------------------------------------------------------
__global__ void __launch_bounds__(512, 1)
conv_mma_kernel(const float* __restrict__ x, const float* __restrict__ wRect) {
    extern __shared__ char smem[];
    const int tid   = threadIdx.x;
    const int lane  = tid & 31;
    const int wid   = tid >> 5;
    const int b     = blockIdx.x >> 2;
    const int mh    = (blockIdx.x >> 1) & 1;
    const int lq    = blockIdx.x & 1;
    const int hbase = mh * 128;
    const int L0    = lq * 1024;
    const int wm    = wid & 7;
    const int wn    = wid >> 3;
    const int grp   = lane >> 2;
    const int tg    = lane & 3;
    const int kq    = tg * 2;

    unsigned long long* TH = (unsigned long long*)(smem + OFF_TH);
    unsigned long long* TL = (unsigned long long*)(smem + OFF_TL);

    // ---- phase 1: stage local x slice, interleaved fp16x4 hi/lo ----
    const float* xb = x + (size_t)b * 4 * LIN;
    for (int l = tid; l < NLOC; l += 512) {
        const int gl = L0 + l;
        unsigned long long hv = 0ull, lv = 0ull;
        if (gl < LIN) {
            unsigned short h0, l0, h1, l1, h2, l2, h3, l3;
            hsplit(xb[gl],           h0, l0);
            hsplit(xb[LIN + gl],     h1, l1);
            hsplit(xb[2 * LIN + gl], h2, l2);
            hsplit(xb[3 * LIN + gl], h3, l3);
            hv = (unsigned long long)h0 | ((unsigned long long)h1 << 16)
               | ((unsigned long long)h2 << 32) | ((unsigned long long)h3 << 48);
            lv = (unsigned long long)l0 | ((unsigned long long)l1 << 16)
               | ((unsigned long long)l2 << 32) | ((unsigned long long)l3 << 48);
        }
        TH[l] = hv;  TL[l] = lv;
    }
    __syncthreads();

    // ---- phase 2: build packed XiQ. slot(2l+p) = {b0h,b1h,b0l,b1l} ----
    {
        const uint32_t* THw = (const uint32_t*)TH;
        const uint32_t* TLw = (const uint32_t*)TL;
        uint4* XiQ = (uint4*)(smem + OFF_XIQ);
        for (int i = tid; i < NQ; i += 512) {
            uint4 q;
            q.x = THw[i];     q.y = THw[i + 4];
            q.z = TLw[i];     q.w = TLw[i + 4];
            XiQ[i] = q;
        }
    }

    // ---- A fragments: 6 x LDG.128 from the pre-packed layout ----
    uint32_t aH[6][4];
    {
        const uint32_t* wa = g_wA + ((size_t)((mh * 8 + wm) * 32 + lane)) * 24;
#pragma unroll
        for (int ks = 0; ks < 6; ++ks)
            *(uint4*)&aH[ks][0] = *(const uint4*)(wa + ks * 4);
    }

    float rb[2];
    rb[0] = wRect[hbase + wm * 16 + grp];
    rb[1] = wRect[hbase + wm * 16 + 8 + grp];

    __syncthreads();

    const uint4* XiQ = (const uint4*)(smem + OFF_XIQ);
    const int sbase = 2 * (wn * 64 + grp + (tg >> 1)) + (tg & 1);
    const int toff  = (wid >> 2) << 1;     // per-warp tile stagger (SMSP-mates differ)

    float mx[2] = {0.f, 0.f};
    float sm[2] = {0.f, 0.f};

    for (int t = 0; t < NTLOC; ++t) {
        const int ta = (t + toff) & 7;
        const int base_t = sbase + 2 * ta * 128;

        float d[8][4];
#pragma unroll
        for (int nt = 0; nt < 8; ++nt) {
            d[nt][0] = rb[0]; d[nt][1] = rb[0];     // bias preloaded
            d[nt][2] = rb[1]; d[nt][3] = rb[1];
        }

#pragma unroll
        for (int ks = 0; ks < 6; ++ks) {
            uint4 q[8];
#pragma unroll
            for (int nt = 0; nt < 8; ++nt)
                q[nt] = XiQ[base_t + 2 * (nt * 8 + 4 * ks)];
#pragma unroll
            for (int nt = 0; nt < 8; ++nt)
                mma_f16(d[nt], aH[ks], q[nt].x, q[nt].y);    // Wh * xh
#pragma unroll
            for (int nt = 0; nt < 8; ++nt)
                mma_f16(d[nt], aH[ks], q[nt].z, q[nt].w);    // Wh * xl
        }

        if (!(lq == 1 && ta == 7)) {
#pragma unroll
            for (int nt = 0; nt < 8; ++nt)
#pragma unroll
                for (int e = 0; e < 4; ++e) {
                    const int rh = e >> 1;
                    const float r = fmaxf(d[nt][e], 0.f);
                    mx[rh] = fmaxf(mx[rh], r);
                    sm[rh] += r;
                }
        } else {
            const int lb = L0 + ta * 128 + wn * 64;
#pragma unroll
            for (int nt = 0; nt < 8; ++nt)
#pragma unroll
                for (int e = 0; e < 4; ++e) {
                    const int rh = e >> 1;
                    const int n  = lb + nt * 8 + kq + (e & 1);
                    const float r = fmaxf(d[nt][e], 0.f);
                    if (n < LOUT) {
                        mx[rh] = fmaxf(mx[rh], r);
                        sm[rh] += r;
                    }
                }
        }
    }

    // ---- lane-group reduce, cross-wn combine, write partials ----
    __syncthreads();
    float* red = (float*)(smem + OFF_RED);
#pragma unroll
    for (int rh = 0; rh < 2; ++rh) {
        float mv = mx[rh], sv = sm[rh];
        mv = fmaxf(mv, __shfl_xor_sync(0xffffffffu, mv, 1));
        sv +=        __shfl_xor_sync(0xffffffffu, sv, 1);
        mv = fmaxf(mv, __shfl_xor_sync(0xffffffffu, mv, 2));
        sv +=        __shfl_xor_sync(0xffffffffu, sv, 2);
        if (tg == 0) {
            const int m = wm * 16 + rh * 8 + grp;
            red[wn * 128 + m]       = mv;
            red[256 + wn * 128 + m] = sv;
        }
    }
    __syncthreads();

    if (tid < 128) {
        const float mv = fmaxf(red[tid], red[128 + tid]);
        const float sv = red[256 + tid] + red[384 + tid];
        float* pp = g_pp + (size_t)(b * 2 + lq) * TWOH;
        pp[hbase + tid]         = mv;
        pp[HNODE + hbase + tid] = sv;     // unscaled sum
    }
}

// ---------------------------------------------------------------------------
// Kernel 2: MLP head, batched GEMV with partial-pool combine in staging.
// ---------------------------------------------------------------------------
__global__ void __launch_bounds__(256)
mlp_kernel(const float* __restrict__ wH, const float* __restrict__ wHB,
           const float* __restrict__ wNeu) {
    __shared__ float4 prow[TWOH];
    __shared__ float  redsm[32];

    const int tid = threadIdx.x;
    const int bt  = blockIdx.x >> 1;
    const int oh  = blockIdx.x & 1;
    const int o   = oh * 256 + tid;
    const int b0  = bt * 4;

    for (int i = tid; i < TWOH; i += 256) {
        float4 v;
        const float inv = 1.0f / LOUT;
#pragma unroll
        for (int j = 0; j < 4; ++j) {
            const float* p0 = g_pp + (size_t)((b0 + j) * 2 + 0) * TWOH;
            const float* p1 = g_pp + (size_t)((b0 + j) * 2 + 1) * TWOH;
            float val = (i < HNODE) ? fmaxf(p0[i], p1[i])
                                    : (p0[i] + p1[i]) * inv;
            ((float*)&v)[j] = val;
        }
        prow[i] = v;
    }
    __syncthreads();

    float a0 = 0.f, a1 = 0.f, a2 = 0.f, a3 = 0.f;
#pragma unroll 8
    for (int i = 0; i < TWOH; ++i) {
        const float w = wH[i * TWOH + o];
        const float4 p = prow[i];
        a0 = fmaf(p.x, w, a0);
        a1 = fmaf(p.y, w, a1);
        a2 = fmaf(p.z, w, a2);
        a3 = fmaf(p.w, w, a3);
    }

    const float hb = wHB[o];
    const float wv = wNeu[o];
    float vals[4];
    vals[0] = fmaxf(a0 + hb, 0.f) * wv;
    vals[1] = fmaxf(a1 + hb, 0.f) * wv;
    vals[2] = fmaxf(a2 + hb, 0.f) * wv;
    vals[3] = fmaxf(a3 + hb, 0.f) * wv;

    const int lane = tid & 31, wid = tid >> 5;
#pragma unroll
    for (int j = 0; j < 4; ++j) {
        float v = vals[j];
        v += __shfl_xor_sync(0xffffffffu, v, 16);
        v += __shfl_xor_sync(0xffffffffu, v, 8);
        v += __shfl_xor_sync(0xffffffffu, v, 4);
        v += __shfl_xor_sync(0xffffffffu, v, 2);
        v += __shfl_xor_sync(0xffffffffu, v, 1);
        if (lane == 0) redsm[j * 8 + wid] = v;
    }
    __syncthreads();

    if (tid < 32) {
        float v = redsm[tid];
        v += __shfl_xor_sync(0xffffffffu, v, 4);
        v += __shfl_xor_sync(0xffffffffu, v, 2);
        v += __shfl_xor_sync(0xffffffffu, v, 1);
        if ((tid & 7) == 0)
            g_part[(b0 + (tid >> 3)) * 2 + oh] = v;
    }
}

// ---------------------------------------------------------------------------
// Kernel 3: out[b] = 0.5*(p0+p1) + wNeuBias
// ---------------------------------------------------------------------------
__global__ void __launch_bounds__(256)
final_kernel(const float* __restrict__ wNB, float* __restrict__ out) {
    const int b = threadIdx.x;
    out[b] = 0.5f * (g_part[2 * b] + g_part[2 * b + 1]) + wNB[0];
}

// ---------------------------------------------------------------------------
// Launch
// ---------------------------------------------------------------------------
extern "C" void kernel_launch(void* const* d_in, const int* in_sizes, int n_in,
                              void* d_out, int out_size) {
    const float* x     = (const float*)d_in[0];
    const float* wConv = (const float*)d_in[1];
    const float* wRect = (const float*)d_in[2];
    const float* wH    = (const float*)d_in[3];
    const float* wHB   = (const float*)d_in[4];
    const float* wNeu  = (const float*)d_in[5];
    const float* wNB   = (const float*)d_in[6];
    float* out = (float*)d_out;

    static int smem_set = 0;
    if (!smem_set) {
        cudaFuncSetAttribute(conv_mma_kernel,
                             cudaFuncAttributeMaxDynamicSharedMemorySize,
                             SMEM_BYTES);
        smem_set = 1;
    }

    prep_w_kernel<<<48, 256>>>(wConv);
    conv_mma_kernel<<<BATCH * 4, 512, SMEM_BYTES>>>(x, wRect);
    mlp_kernel<<<128, 256>>>(wH, wHB, wNeu);
    final_kernel<<<1, 256>>>(wNB, out);
}

// round 9
// speedup vs baseline: 1.5132x; 1.0280x over previous
#include <cuda_runtime.h>
#include <cuda_fp16.h>
#include <cstdint>

// ---------------------------------------------------------------------------
// Problem constants
// ---------------------------------------------------------------------------
#define BATCH  256
#define LIN    2048
#define HNODE  256
#define GLEN   24
#define LOUT   2025
#define TWOH   512
#define KDIM   96
#define NTLOC  8              // tiles of 128 l-positions per CTA (l-half)
#define NQ     2096           // XiQ slots staged per CTA
#define SLOTS  4160           // g_xq slots per batch (covers l < 2080)

// ---------------------------------------------------------------------------
// Shared memory: XiQ tile (33536 B); RED overlays it after the main loop.
// ---------------------------------------------------------------------------
#define SMEM_BYTES 33536

__device__ float    g_pp[BATCH * 2 * TWOH];   // per (b, l-half): [max | sum]
__device__ uint32_t g_wA[2 * 8 * 32 * 24];    // pre-packed fp16 A-fragments
__device__ uint4    g_xq[BATCH * SLOTS];      // pre-packed b-fragment quads

// ---------------------------------------------------------------------------
// Helpers
// ---------------------------------------------------------------------------
static __device__ __forceinline__ void hsplit(float v, unsigned short& hi,
                                              unsigned short& lo) {
    __half h = __float2half(v);
    __half l = __float2half(v - __half2float(h));
    hi = __half_as_ushort(h);
    lo = __half_as_ushort(l);
}

static __device__ __forceinline__ void mma_f16(float* d, const uint32_t* a,
                                               uint32_t b0, uint32_t b1) {
    asm volatile(
        "mma.sync.aligned.m16n8k16.row.col.f32.f16.f16.f32 "
        "{%0,%1,%2,%3}, {%4,%5,%6,%7}, {%8,%9}, {%0,%1,%2,%3};"
        : "+f"(d[0]), "+f"(d[1]), "+f"(d[2]), "+f"(d[3])
        : "r"(a[0]), "r"(a[1]), "r"(a[2]), "r"(a[3]), "r"(b0), "r"(b1));
}

// ---------------------------------------------------------------------------
// Kernel 0: unified prep.
//  blocks [0, 4160):    build g_xq — slot s of batch b: s = 2l+p holds
//                       {xh(c2p,l)|xh(c2p+1,l), xh@l+2, xl@l, xl@l+2}
//  blocks [4160, 4208): build g_wA — lane-major fp16 A-fragments
// ---------------------------------------------------------------------------
__global__ void __launch_bounds__(256)
prep_kernel(const float* __restrict__ x, const float* __restrict__ wConv) {
    const int bid = blockIdx.x;
    const int tid = threadIdx.x;

    if (bid < 4160) {
        const int id = bid * 256 + tid;          // < 256*4160
        const int b  = id / SLOTS;
        const int s  = id % SLOTS;
        const int l  = s >> 1;
        const int p  = s & 1;
        const float* xb = x + (size_t)b * 4 * LIN + (size_t)(2 * p) * LIN;

        float f00 = 0.f, f10 = 0.f, f01 = 0.f, f11 = 0.f;
        if (l < LIN)     { f00 = xb[l];       f10 = xb[LIN + l]; }
        if (l + 2 < LIN) { f01 = xb[l + 2];   f11 = xb[LIN + l + 2]; }

        unsigned short h00, l00, h10, l10, h01, l01, h11, l11;
        hsplit(f00, h00, l00);
        hsplit(f10, h10, l10);
        hsplit(f01, h01, l01);
        hsplit(f11, h11, l11);

        uint4 q;
        q.x = (uint32_t)h00 | ((uint32_t)h10 << 16);
        q.y = (uint32_t)h01 | ((uint32_t)h11 << 16);
        q.z = (uint32_t)l00 | ((uint32_t)l10 << 16);
        q.w = (uint32_t)l01 | ((uint32_t)l11 << 16);
        g_xq[id] = q;
    } else {
        const int id = (bid - 4160) * 256 + tid;   // < 12288
        const int mh   = id / 6144;
        const int rem  = id % 6144;
        const int wm   = rem / 768;
        const int rem2 = rem % 768;
        const int lane = rem2 / 24;
        const int j    = rem2 % 24;
        const int ks   = j >> 2;
        const int rr   = j & 3;
        const int grp  = lane >> 2;
        const int tg   = lane & 3;

        const int r  = wm * 16 + grp + (rr & 1) * 8;
        const int k0 = ks * 16 + tg * 2 + (rr >> 1) * 8;        // even
        const int base = (mh * 128 + r) * KDIM + (k0 >> 2);     // k = 4g + c
        const float f0 = wConv[base + (k0 & 3) * GLEN];
        const float f1 = wConv[base + ((k0 & 3) + 1) * GLEN];
        const unsigned short h0 = __half_as_ushort(__float2half(f0));
        const unsigned short h1 = __half_as_ushort(__float2half(f1));
        g_wA[id] = (uint32_t)h0 | ((uint32_t)h1 << 16);
    }
}

// ---------------------------------------------------------------------------
// Kernel 1: implicit-GEMM conv, 2-term fp16 split, prologue = pure copy.
// Grid: 1024 CTAs = (batch, h-half, l-half). 512 threads = 16 warps,
// warp grid 8(M) x 2(N), warp tile 16(h) x 64(l). Per-warp tile stagger.
// ---------------------------------------------------------------------------
__global__ void __launch_bounds__(512, 1)
conv_mma_kernel(const float* __restrict__ wRect) {
    extern __shared__ char smem[];
    const int tid   = threadIdx.x;
    const int lane  = tid & 31;
    const int wid   = tid >> 5;
    const int b     = blockIdx.x >> 2;
    const int mh    = (blockIdx.x >> 1) & 1;
    const int lq    = blockIdx.x & 1;
    const int hbase = mh * 128;
    const int L0    = lq * 1024;
    const int wm    = wid & 7;
    const int wn    = wid >> 3;
    const int grp   = lane >> 2;
    const int tg    = lane & 3;
    const int kq    = tg * 2;

    // ---- prologue: copy this CTA's XiQ window from the prepacked table ----
    {
        const uint4* src = g_xq + (size_t)b * SLOTS + 2 * L0;
        uint4* dst = (uint4*)smem;
        for (int i = tid; i < NQ; i += 512) dst[i] = src[i];
    }

    // ---- A fragments: 6 x LDG.128 from the pre-packed layout ----
    uint32_t aH[6][4];
    {
        const uint32_t* wa = g_wA + ((size_t)((mh * 8 + wm) * 32 + lane)) * 24;
#pragma unroll
        for (int ks = 0; ks < 6; ++ks)
            *(uint4*)&aH[ks][0] = *(const uint4*)(wa + ks * 4);
    }

    float rb[2];
    rb[0] = wRect[hbase + wm * 16 + grp];
    rb[1] = wRect[hbase + wm * 16 + 8 + grp];

    __syncthreads();

    const uint4* XiQ = (const uint4*)smem;
    const int sbase = 2 * (wn * 64 + grp + (tg >> 1)) + (tg & 1);
    const int toff  = (wid >> 2) << 1;    // SMSP-mates get different tiles

    float mx[2] = {0.f, 0.f};
    float sm[2] = {0.f, 0.f};

    for (int t = 0; t < NTLOC; ++t) {
        const int ta = (t + toff) & 7;
        const int base_t = sbase + 2 * ta * 128;

        float d[8][4];
#pragma unroll
        for (int nt = 0; nt < 8; ++nt) {
            d[nt][0] = rb[0]; d[nt][1] = rb[0];
            d[nt][2] = rb[1]; d[nt][3] = rb[1];
        }

#pragma unroll
        for (int ks = 0; ks < 6; ++ks) {
            uint4 q[8];
#pragma unroll
            for (int nt = 0; nt < 8; ++nt)
                q[nt] = XiQ[base_t + 2 * (nt * 8 + 4 * ks)];
#pragma unroll
            for (int nt = 0; nt < 8; ++nt)
                mma_f16(d[nt], aH[ks], q[nt].x, q[nt].y);    // Wh * xh
#pragma unroll
            for (int nt = 0; nt < 8; ++nt)
                mma_f16(d[nt], aH[ks], q[nt].z, q[nt].w);    // Wh * xl
        }

        if (!(lq == 1 && ta == 7)) {
#pragma unroll
            for (int nt = 0; nt < 8; ++nt)
#pragma unroll
                for (int e = 0; e < 4; ++e) {
                    const int rh = e >> 1;
                    const float r = fmaxf(d[nt][e], 0.f);
                    mx[rh] = fmaxf(mx[rh], r);
                    sm[rh] += r;
                }
        } else {
            const int lb = L0 + ta * 128 + wn * 64;
#pragma unroll
            for (int nt = 0; nt < 8; ++nt)
#pragma unroll
                for (int e = 0; e < 4; ++e) {
                    const int rh = e >> 1;
                    const int n  = lb + nt * 8 + kq + (e & 1);
                    const float r = fmaxf(d[nt][e], 0.f);
                    if (n < LOUT) {
                        mx[rh] = fmaxf(mx[rh], r);
                        sm[rh] += r;
                    }
                }
        }
    }

    // ---- lane-group reduce, cross-wn combine, write partials ----
    __syncthreads();                       // all XiQ reads done
    float* red = (float*)smem;             // overlay
#pragma unroll
    for (int rh = 0; rh < 2; ++rh) {
        float mv = mx[rh], sv = sm[rh];
        mv = fmaxf(mv, __shfl_xor_sync(0xffffffffu, mv, 1));
        sv +=        __shfl_xor_sync(0xffffffffu, sv, 1);
        mv = fmaxf(mv, __shfl_xor_sync(0xffffffffu, mv, 2));
        sv +=        __shfl_xor_sync(0xffffffffu, sv, 2);
        if (tg == 0) {
            const int m = wm * 16 + rh * 8 + grp;
            red[wn * 128 + m]       = mv;
            red[256 + wn * 128 + m] = sv;
        }
    }
    __syncthreads();

    if (tid < 128) {
        const float mv = fmaxf(red[tid], red[128 + tid]);
        const float sv = red[256 + tid] + red[384 + tid];
        float* pp = g_pp + (size_t)(b * 2 + lq) * TWOH;
        pp[hbase + tid]         = mv;
        pp[HNODE + hbase + tid] = sv;      // unscaled sum
    }
}

// ---------------------------------------------------------------------------
// Kernel 2: fused MLP head. Grid 64 CTAs x 512 threads: each CTA handles
// 4 batches x all 512 outputs, reduces in-CTA, writes out directly.
// ---------------------------------------------------------------------------
__global__ void __launch_bounds__(512)
mlp_kernel(const float* __restrict__ wH, const float* __restrict__ wHB,
           const float* __restrict__ wNeu, const float* __restrict__ wNB,
           float* __restrict__ out) {
    __shared__ float4 prow[TWOH];
    __shared__ float  redsm[64];

    const int tid = threadIdx.x;
    const int b0  = blockIdx.x * 4;
    const int o   = tid;

    // stage pool rows (combine l-half partials: max / avg)
    {
        const int i = tid;
        const float inv = 1.0f / LOUT;
        float4 v;
#pragma unroll
        for (int j = 0; j < 4; ++j) {
            const float* p0 = g_pp + (size_t)((b0 + j) * 2 + 0) * TWOH;
            const float* p1 = g_pp + (size_t)((b0 + j) * 2 + 1) * TWOH;
            ((float*)&v)[j] = (i < HNODE) ? fmaxf(p0[i], p1[i])
                                          : (p0[i] + p1[i]) * inv;
        }
        prow[i] = v;
    }
    __syncthreads();

    float a0 = 0.f, a1 = 0.f, a2 = 0.f, a3 = 0.f;
#pragma unroll 8
    for (int i = 0; i < TWOH; ++i) {
        const float w = wH[i * TWOH + o];
        const float4 p = prow[i];
        a0 = fmaf(p.x, w, a0);
        a1 = fmaf(p.y, w, a1);
        a2 = fmaf(p.z, w, a2);
        a3 = fmaf(p.w, w, a3);
    }

    const float hb = wHB[o];
    const float wv = wNeu[o];
    float vals[4];
    vals[0] = fmaxf(a0 + hb, 0.f) * wv;
    vals[1] = fmaxf(a1 + hb, 0.f) * wv;
    vals[2] = fmaxf(a2 + hb, 0.f) * wv;
    vals[3] = fmaxf(a3 + hb, 0.f) * wv;

    const int lane = tid & 31, wid = tid >> 5;
#pragma unroll
    for (int j = 0; j < 4; ++j) {
        float v = vals[j];
        v += __shfl_xor_sync(0xffffffffu, v, 16);
        v += __shfl_xor_sync(0xffffffffu, v, 8);
        v += __shfl_xor_sync(0xffffffffu, v, 4);
        v += __shfl_xor_sync(0xffffffffu, v, 2);
        v += __shfl_xor_sync(0xffffffffu, v, 1);
        if (lane == 0) redsm[j * 16 + wid] = v;
    }
    __syncthreads();

    if (tid < 4) {
        float s = 0.f;
#pragma unroll
        for (int i = 0; i < 16; ++i) s += redsm[tid * 16 + i];
        out[b0 + tid] = 0.5f * s + wNB[0];
    }
}

// ---------------------------------------------------------------------------
// Launch
// ---------------------------------------------------------------------------
extern "C" void kernel_launch(void* const* d_in, const int* in_sizes, int n_in,
                              void* d_out, int out_size) {
    const float* x     = (const float*)d_in[0];
    const float* wConv = (const float*)d_in[1];
    const float* wRect = (const float*)d_in[2];
    const float* wH    = (const float*)d_in[3];
    const float* wHB   = (const float*)d_in[4];
    const float* wNeu  = (const float*)d_in[5];
    const float* wNB   = (const float*)d_in[6];
    float* out = (float*)d_out;

    static int smem_set = 0;
    if (!smem_set) {
        cudaFuncSetAttribute(conv_mma_kernel,
                             cudaFuncAttributeMaxDynamicSharedMemorySize,
                             SMEM_BYTES);
        smem_set = 1;
    }

    prep_kernel<<<4208, 256>>>(x, wConv);
    conv_mma_kernel<<<BATCH * 4, 512, SMEM_BYTES>>>(wRect);
    mlp_kernel<<<64, 512>>>(wH, wHB, wNeu, wNB, out);
}

// round 10
// speedup vs baseline: 1.5349x; 1.0143x over previous
#include <cuda_runtime.h>
#include <cuda_fp16.h>
#include <cstdint>

// ---------------------------------------------------------------------------
// Problem constants
// ---------------------------------------------------------------------------
#define BATCH  256
#define LIN    2048
#define HNODE  256
#define GLEN   24
#define LOUT   2025
#define TWOH   512
#define KDIM   96
#define NTLOC  8              // tiles of 128 l-positions per CTA (l-half)
#define NQ     2096           // XiQ slots staged per CTA
#define SLOTS  4160           // g_xq slots per batch (covers l < 2080)

#define SMEM_BYTES 33536

__device__ float    g_pp[BATCH * 2 * TWOH];   // per (b, l-half): [max | sum]
__device__ uint32_t g_wA[2 * 8 * 32 * 24];    // pre-packed fp16 A-fragments
__device__ uint4    g_xq[BATCH * SLOTS];      // pre-packed b-fragment quads

// ---------------------------------------------------------------------------
// Helpers
// ---------------------------------------------------------------------------
static __device__ __forceinline__ void hsplit(float v, unsigned short& hi,
                                              unsigned short& lo) {
    __half h = __float2half(v);
    __half l = __float2half(v - __half2float(h));
    hi = __half_as_ushort(h);
    lo = __half_as_ushort(l);
}

static __device__ __forceinline__ void mma_f16(float* d, const uint32_t* a,
                                               uint32_t b0, uint32_t b1) {
    asm volatile(
        "mma.sync.aligned.m16n8k16.row.col.f32.f16.f16.f32 "
        "{%0,%1,%2,%3}, {%4,%5,%6,%7}, {%8,%9}, {%0,%1,%2,%3};"
        : "+f"(d[0]), "+f"(d[1]), "+f"(d[2]), "+f"(d[3])
        : "r"(a[0]), "r"(a[1]), "r"(a[2]), "r"(a[3]), "r"(b0), "r"(b1));
}

// ---------------------------------------------------------------------------
// Kernel 0: unified prep (g_xq b-fragment table + g_wA A-fragments)
// ---------------------------------------------------------------------------
__global__ void __launch_bounds__(256)
prep_kernel(const float* __restrict__ x, const float* __restrict__ wConv) {
    const int bid = blockIdx.x;
    const int tid = threadIdx.x;

    if (bid < 4160) {
        const int id = bid * 256 + tid;
        const int b  = id / SLOTS;
        const int s  = id % SLOTS;
        const int l  = s >> 1;
        const int p  = s & 1;
        const float* xb = x + (size_t)b * 4 * LIN + (size_t)(2 * p) * LIN;

        float f00 = 0.f, f10 = 0.f, f01 = 0.f, f11 = 0.f;
        if (l < LIN)     { f00 = xb[l];       f10 = xb[LIN + l]; }
        if (l + 2 < LIN) { f01 = xb[l + 2];   f11 = xb[LIN + l + 2]; }

        unsigned short h00, l00, h10, l10, h01, l01, h11, l11;
        hsplit(f00, h00, l00);
        hsplit(f10, h10, l10);
        hsplit(f01, h01, l01);
        hsplit(f11, h11, l11);

        uint4 q;
        q.x = (uint32_t)h00 | ((uint32_t)h10 << 16);
        q.y = (uint32_t)h01 | ((uint32_t)h11 << 16);
        q.z = (uint32_t)l00 | ((uint32_t)l10 << 16);
        q.w = (uint32_t)l01 | ((uint32_t)l11 << 16);
        g_xq[id] = q;
    } else {
        const int id = (bid - 4160) * 256 + tid;   // < 12288
        const int mh   = id / 6144;
        const int rem  = id % 6144;
        const int wm   = rem / 768;
        const int rem2 = rem % 768;
        const int lane = rem2 / 24;
        const int j    = rem2 % 24;
        const int ks   = j >> 2;
        const int rr   = j & 3;
        const int grp  = lane >> 2;
        const int tg   = lane & 3;

        const int r  = wm * 16 + grp + (rr & 1) * 8;
        const int k0 = ks * 16 + tg * 2 + (rr >> 1) * 8;        // even
        const int base = (mh * 128 + r) * KDIM + (k0 >> 2);     // k = 4g + c
        const float f0 = wConv[base + (k0 & 3) * GLEN];
        const float f1 = wConv[base + ((k0 & 3) + 1) * GLEN];
        const unsigned short h0 = __half_as_ushort(__float2half(f0));
        const unsigned short h1 = __half_as_ushort(__float2half(f1));
        g_wA[id] = (uint32_t)h0 | ((uint32_t)h1 << 16);
    }
}

// ---------------------------------------------------------------------------
// Kernel 1: implicit-GEMM conv, 2-term fp16 split.
// Diagonal-reuse inner loop: slot(nt,ks) = base + 8*(2nt+ks), so only 20
// distinct LDS.128 per warp per tile (10 even-parity u, 10 odd) vs 48.
// Grid: 1024 CTAs = (batch, h-half, l-half). 512 threads = 16 warps,
// warp grid 8(M) x 2(N), warp tile 16(h) x 64(l). Per-warp tile stagger.
// ---------------------------------------------------------------------------
__global__ void __launch_bounds__(512, 1)
conv_mma_kernel(const float* __restrict__ wRect) {
    extern __shared__ char smem[];
    const int tid   = threadIdx.x;
    const int lane  = tid & 31;
    const int wid   = tid >> 5;
    const int b     = blockIdx.x >> 2;
    const int mh    = (blockIdx.x >> 1) & 1;
    const int lq    = blockIdx.x & 1;
    const int hbase = mh * 128;
    const int L0    = lq * 1024;
    const int wm    = wid & 7;
    const int wn    = wid >> 3;
    const int grp   = lane >> 2;
    const int tg    = lane & 3;
    const int kq    = tg * 2;

    // ---- prologue: copy this CTA's XiQ window from the prepacked table ----
    {
        const uint4* src = g_xq + (size_t)b * SLOTS + 2 * L0;
        uint4* dst = (uint4*)smem;
        for (int i = tid; i < NQ; i += 512) dst[i] = src[i];
    }

    // ---- A fragments: 6 x LDG.128 from the pre-packed layout ----
    uint32_t aH[6][4];
    {
        const uint32_t* wa = g_wA + ((size_t)((mh * 8 + wm) * 32 + lane)) * 24;
#pragma unroll
        for (int ks = 0; ks < 6; ++ks)
            *(uint4*)&aH[ks][0] = *(const uint4*)(wa + ks * 4);
    }

    float rb[2];
    rb[0] = wRect[hbase + wm * 16 + grp];
    rb[1] = wRect[hbase + wm * 16 + 8 + grp];

    __syncthreads();

    const uint4* XiQ = (const uint4*)smem;
    const int sbase = 2 * (wn * 64 + grp + (tg >> 1)) + (tg & 1);
    const int toff  = (wid >> 2) << 1;    // SMSP-mates get different tiles

    float mx[2] = {0.f, 0.f};
    float sm[2] = {0.f, 0.f};

    for (int t = 0; t < NTLOC; ++t) {
        const int ta = (t + toff) & 7;
        const int base_t = sbase + 2 * ta * 128;

        float d[8][4];
#pragma unroll
        for (int nt = 0; nt < 8; ++nt) {
            d[nt][0] = rb[0]; d[nt][1] = rb[0];
            d[nt][2] = rb[1]; d[nt][3] = rb[1];
        }

        uint4 q[10];

        // ---- even parity: u = 0,2,..,18 -> serves ks = 0,2,4 ----
#pragma unroll
        for (int j = 0; j < 10; ++j)
            q[j] = XiQ[base_t + 16 * j];
#pragma unroll
        for (int kk = 0; kk < 3; ++kk) {          // ks = 2*kk
#pragma unroll
            for (int nt = 0; nt < 8; ++nt)
                mma_f16(d[nt], aH[2 * kk], q[nt + kk].x, q[nt + kk].y);
#pragma unroll
            for (int nt = 0; nt < 8; ++nt)
                mma_f16(d[nt], aH[2 * kk], q[nt + kk].z, q[nt + kk].w);
        }

        // ---- odd parity: u = 1,3,..,19 -> serves ks = 1,3,5 ----
#pragma unroll
        for (int j = 0; j < 10; ++j)
            q[j] = XiQ[base_t + 8 + 16 * j];
#pragma unroll
        for (int kk = 0; kk < 3; ++kk) {          // ks = 2*kk + 1
#pragma unroll
            for (int nt = 0; nt < 8; ++nt)
                mma_f16(d[nt], aH[2 * kk + 1], q[nt + kk].x, q[nt + kk].y);
#pragma unroll
            for (int nt = 0; nt < 8; ++nt)
                mma_f16(d[nt], aH[2 * kk + 1], q[nt + kk].z, q[nt + kk].w);
        }

        if (!(lq == 1 && ta == 7)) {
#pragma unroll
            for (int nt = 0; nt < 8; ++nt)
#pragma unroll
                for (int e = 0; e < 4; ++e) {
                    const int rh = e >> 1;
                    const float r = fmaxf(d[nt][e], 0.f);
                    mx[rh] = fmaxf(mx[rh], r);
                    sm[rh] += r;
                }
        } else {
            const int lb = L0 + ta * 128 + wn * 64;
#pragma unroll
            for (int nt = 0; nt < 8; ++nt)
#pragma unroll
                for (int e = 0; e < 4; ++e) {
                    const int rh = e >> 1;
                    const int n  = lb + nt * 8 + kq + (e & 1);
                    const float r = fmaxf(d[nt][e], 0.f);
                    if (n < LOUT) {
                        mx[rh] = fmaxf(mx[rh], r);
                        sm[rh] += r;
                    }
                }
        }
    }

    // ---- lane-group reduce, cross-wn combine, write partials ----
    __syncthreads();
    float* red = (float*)smem;             // overlay
#pragma unroll
    for (int rh = 0; rh < 2; ++rh) {
        float mv = mx[rh], sv = sm[rh];
        mv = fmaxf(mv, __shfl_xor_sync(0xffffffffu, mv, 1));
        sv +=        __shfl_xor_sync(0xffffffffu, sv, 1);
        mv = fmaxf(mv, __shfl_xor_sync(0xffffffffu, mv, 2));
        sv +=        __shfl_xor_sync(0xffffffffu, sv, 2);
        if (tg == 0) {
            const int m = wm * 16 + rh * 8 + grp;
            red[wn * 128 + m]       = mv;
            red[256 + wn * 128 + m] = sv;
        }
    }
    __syncthreads();

    if (tid < 128) {
        const float mv = fmaxf(red[tid], red[128 + tid]);
        const float sv = red[256 + tid] + red[384 + tid];
        float* pp = g_pp + (size_t)(b * 2 + lq) * TWOH;
        pp[hbase + tid]         = mv;
        pp[HNODE + hbase + tid] = sv;      // unscaled sum
    }
}

// ---------------------------------------------------------------------------
// Kernel 2: fused MLP head. 64 CTAs x 512 threads, 4 batches each.
// ---------------------------------------------------------------------------
__global__ void __launch_bounds__(512)
mlp_kernel(const float* __restrict__ wH, const float* __restrict__ wHB,
           const float* __restrict__ wNeu, const float* __restrict__ wNB,
           float* __restrict__ out) {
    __shared__ float4 prow[TWOH];
    __shared__ float  redsm[64];

    const int tid = threadIdx.x;
    const int b0  = blockIdx.x * 4;
    const int o   = tid;

    {
        const int i = tid;
        const float inv = 1.0f / LOUT;
        float4 v;
#pragma unroll
        for (int j = 0; j < 4; ++j) {
            const float* p0 = g_pp + (size_t)((b0 + j) * 2 + 0) * TWOH;
            const float* p1 = g_pp + (size_t)((b0 + j) * 2 + 1) * TWOH;
            ((float*)&v)[j] = (i < HNODE) ? fmaxf(p0[i], p1[i])
                                          : (p0[i] + p1[i]) * inv;
        }
        prow[i] = v;
    }
    __syncthreads();

    float a0 = 0.f, a1 = 0.f, a2 = 0.f, a3 = 0.f;
#pragma unroll 8
    for (int i = 0; i < TWOH; ++i) {
        const float w = wH[i * TWOH + o];
        const float4 p = prow[i];
        a0 = fmaf(p.x, w, a0);
        a1 = fmaf(p.y, w, a1);
        a2 = fmaf(p.z, w, a2);
        a3 = fmaf(p.w, w, a3);
    }

    const float hb = wHB[o];
    const float wv = wNeu[o];
    float vals[4];
    vals[0] = fmaxf(a0 + hb, 0.f) * wv;
    vals[1] = fmaxf(a1 + hb, 0.f) * wv;
    vals[2] = fmaxf(a2 + hb, 0.f) * wv;
    vals[3] = fmaxf(a3 + hb, 0.f) * wv;

    const int lane = tid & 31, wid = tid >> 5;
#pragma unroll
    for (int j = 0; j < 4; ++j) {
        float v = vals[j];
        v += __shfl_xor_sync(0xffffffffu, v, 16);
        v += __shfl_xor_sync(0xffffffffu, v, 8);
        v += __shfl_xor_sync(0xffffffffu, v, 4);
        v += __shfl_xor_sync(0xffffffffu, v, 2);
        v += __shfl_xor_sync(0xffffffffu, v, 1);
        if (lane == 0) redsm[j * 16 + wid] = v;
    }
    __syncthreads();

    if (tid < 4) {
        float s = 0.f;
#pragma unroll
        for (int i = 0; i < 16; ++i) s += redsm[tid * 16 + i];
        out[b0 + tid] = 0.5f * s + wNB[0];
    }
}

// ---------------------------------------------------------------------------
// Launch
// ---------------------------------------------------------------------------
extern "C" void kernel_launch(void* const* d_in, const int* in_sizes, int n_in,
                              void* d_out, int out_size) {
    const float* x     = (const float*)d_in[0];
    const float* wConv = (const float*)d_in[1];
    const float* wRect = (const float*)d_in[2];
    const float* wH    = (const float*)d_in[3];
    const float* wHB   = (const float*)d_in[4];
    const float* wNeu  = (const float*)d_in[5];
    const float* wNB   = (const float*)d_in[6];
    float* out = (float*)d_out;

    static int smem_set = 0;
    if (!smem_set) {
        cudaFuncSetAttribute(conv_mma_kernel,
                             cudaFuncAttributeMaxDynamicSharedMemorySize,
                             SMEM_BYTES);
        smem_set = 1;
    }

    prep_kernel<<<4208, 256>>>(x, wConv);
    conv_mma_kernel<<<BATCH * 4, 512, SMEM_BYTES>>>(wRect);
    mlp_kernel<<<64, 512>>>(wH, wHB, wNeu, wNB, out);
}

// round 11
// speedup vs baseline: 1.6138x; 1.0514x over previous
#include <cuda_runtime.h>
#include <cuda_fp16.h>
#include <cstdint>

// ---------------------------------------------------------------------------
// Problem constants
// ---------------------------------------------------------------------------
#define BATCH  256
#define LIN    2048
#define HNODE  256
#define GLEN   24
#define LOUT   2025
#define TWOH   512
#define KDIM   96
#define NTLOC  8              // tiles of 128 l-positions per CTA (l-half)
#define SLOTS  4160           // g_xq slots per batch (covers l < 2080)

__device__ float    g_pp[BATCH * 2 * TWOH];   // per (b, l-half): [max | sum]
__device__ uint32_t g_wA[2 * 8 * 32 * 24];    // pre-packed fp16 A-fragments
__device__ uint4    g_xq[BATCH * SLOTS];      // pre-packed b-fragment quads

// ---------------------------------------------------------------------------
// Helpers
// ---------------------------------------------------------------------------
static __device__ __forceinline__ void hsplit(float v, unsigned short& hi,
                                              unsigned short& lo) {
    __half h = __float2half(v);
    __half l = __float2half(v - __half2float(h));
    hi = __half_as_ushort(h);
    lo = __half_as_ushort(l);
}

static __device__ __forceinline__ void mma_f16(float* d, const uint32_t* a,
                                               uint32_t b0, uint32_t b1) {
    asm volatile(
        "mma.sync.aligned.m16n8k16.row.col.f32.f16.f16.f32 "
        "{%0,%1,%2,%3}, {%4,%5,%6,%7}, {%8,%9}, {%0,%1,%2,%3};"
        : "+f"(d[0]), "+f"(d[1]), "+f"(d[2]), "+f"(d[3])
        : "r"(a[0]), "r"(a[1]), "r"(a[2]), "r"(a[3]), "r"(b0), "r"(b1));
}

// ---------------------------------------------------------------------------
// Kernel 0: unified prep (g_xq b-fragment table + g_wA A-fragments)
// ---------------------------------------------------------------------------
__global__ void __launch_bounds__(256)
prep_kernel(const float* __restrict__ x, const float* __restrict__ wConv) {
    const int bid = blockIdx.x;
    const int tid = threadIdx.x;

    if (bid < 4160) {
        const int id = bid * 256 + tid;
        const int b  = id / SLOTS;
        const int s  = id % SLOTS;
        const int l  = s >> 1;
        const int p  = s & 1;
        const float* xb = x + (size_t)b * 4 * LIN + (size_t)(2 * p) * LIN;

        float f00 = 0.f, f10 = 0.f, f01 = 0.f, f11 = 0.f;
        if (l < LIN)     { f00 = xb[l];       f10 = xb[LIN + l]; }
        if (l + 2 < LIN) { f01 = xb[l + 2];   f11 = xb[LIN + l + 2]; }

        unsigned short h00, l00, h10, l10, h01, l01, h11, l11;
        hsplit(f00, h00, l00);
        hsplit(f10, h10, l10);
        hsplit(f01, h01, l01);
        hsplit(f11, h11, l11);

        uint4 q;
        q.x = (uint32_t)h00 | ((uint32_t)h10 << 16);
        q.y = (uint32_t)h01 | ((uint32_t)h11 << 16);
        q.z = (uint32_t)l00 | ((uint32_t)l10 << 16);
        q.w = (uint32_t)l01 | ((uint32_t)l11 << 16);
        g_xq[id] = q;
    } else {
        const int id = (bid - 4160) * 256 + tid;   // < 12288
        const int mh   = id / 6144;
        const int rem  = id % 6144;
        const int wm   = rem / 768;
        const int rem2 = rem % 768;
        const int lane = rem2 / 24;
        const int j    = rem2 % 24;
        const int ks   = j >> 2;
        const int rr   = j & 3;
        const int grp  = lane >> 2;
        const int tg   = lane & 3;

        const int r  = wm * 16 + grp + (rr & 1) * 8;
        const int k0 = ks * 16 + tg * 2 + (rr >> 1) * 8;        // even
        const int base = (mh * 128 + r) * KDIM + (k0 >> 2);     // k = 4g + c
        const float f0 = wConv[base + (k0 & 3) * GLEN];
        const float f1 = wConv[base + ((k0 & 3) + 1) * GLEN];
        const unsigned short h0 = __half_as_ushort(__float2half(f0));
        const unsigned short h1 = __half_as_ushort(__float2half(f1));
        g_wA[id] = (uint32_t)h0 | ((uint32_t)h1 << 16);
    }
}

// ---------------------------------------------------------------------------
// Kernel 1: implicit-GEMM conv, 2-term fp16 split.
// NO smem staging: b-fragments load directly from the prepacked gmem table
// (33.5 KB window per CTA -> L1-resident, ~60x reuse). No prologue barrier.
// Diagonal reuse: slot(nt,ks) = base + 8*(2nt+ks) -> 20 LDG.128/warp/tile.
// Grid: 1024 CTAs = (batch, h-half, l-half). 512 threads = 16 warps,
// warp grid 8(M) x 2(N), warp tile 16(h) x 64(l). Per-warp tile stagger.
// ---------------------------------------------------------------------------
__global__ void __launch_bounds__(512, 1)
conv_mma_kernel(const float* __restrict__ wRect) {
    __shared__ float red[512];

    const int tid   = threadIdx.x;
    const int lane  = tid & 31;
    const int wid   = tid >> 5;
    const int b     = blockIdx.x >> 2;
    const int mh    = (blockIdx.x >> 1) & 1;
    const int lq    = blockIdx.x & 1;
    const int hbase = mh * 128;
    const int L0    = lq * 1024;
    const int wm    = wid & 7;
    const int wn    = wid >> 3;
    const int grp   = lane >> 2;
    const int tg    = lane & 3;
    const int kq    = tg * 2;

    // ---- A fragments: 6 x LDG.128 from the pre-packed layout ----
    uint32_t aH[6][4];
    {
        const uint32_t* wa = g_wA + ((size_t)((mh * 8 + wm) * 32 + lane)) * 24;
#pragma unroll
        for (int ks = 0; ks < 6; ++ks)
            *(uint4*)&aH[ks][0] = *(const uint4*)(wa + ks * 4);
    }

    float rb[2];
    rb[0] = wRect[hbase + wm * 16 + grp];
    rb[1] = wRect[hbase + wm * 16 + 8 + grp];

    // b-fragment table window for this CTA (gmem; L1-cached on reuse)
    const uint4* XiQ = g_xq + (size_t)b * SLOTS + 2 * L0;
    const int sbase = 2 * (wn * 64 + grp + (tg >> 1)) + (tg & 1);
    const int toff  = (wid >> 2) << 1;    // SMSP-mates get different tiles

    float mx[2] = {0.f, 0.f};
    float sm[2] = {0.f, 0.f};

    for (int t = 0; t < NTLOC; ++t) {
        const int ta = (t + toff) & 7;
        const int base_t = sbase + 2 * ta * 128;

        float d[8][4];
#pragma unroll
        for (int nt = 0; nt < 8; ++nt) {
            d[nt][0] = rb[0]; d[nt][1] = rb[0];
            d[nt][2] = rb[1]; d[nt][3] = rb[1];
        }

        uint4 q[10];

        // ---- even parity: u = 0,2,..,18 -> serves ks = 0,2,4 ----
#pragma unroll
        for (int j = 0; j < 10; ++j)
            q[j] = XiQ[base_t + 16 * j];
#pragma unroll
        for (int kk = 0; kk < 3; ++kk) {          // ks = 2*kk
#pragma unroll
            for (int nt = 0; nt < 8; ++nt)
                mma_f16(d[nt], aH[2 * kk], q[nt + kk].x, q[nt + kk].y);
#pragma unroll
            for (int nt = 0; nt < 8; ++nt)
                mma_f16(d[nt], aH[2 * kk], q[nt + kk].z, q[nt + kk].w);
        }

        // ---- odd parity: u = 1,3,..,19 -> serves ks = 1,3,5 ----
#pragma unroll
        for (int j = 0; j < 10; ++j)
            q[j] = XiQ[base_t + 8 + 16 * j];
#pragma unroll
        for (int kk = 0; kk < 3; ++kk) {          // ks = 2*kk + 1
#pragma unroll
            for (int nt = 0; nt < 8; ++nt)
                mma_f16(d[nt], aH[2 * kk + 1], q[nt + kk].x, q[nt + kk].y);
#pragma unroll
            for (int nt = 0; nt < 8; ++nt)
                mma_f16(d[nt], aH[2 * kk + 1], q[nt + kk].z, q[nt + kk].w);
        }

        if (!(lq == 1 && ta == 7)) {
#pragma unroll
            for (int nt = 0; nt < 8; ++nt)
#pragma unroll
                for (int e = 0; e < 4; ++e) {
                    const int rh = e >> 1;
                    const float r = fmaxf(d[nt][e], 0.f);
                    mx[rh] = fmaxf(mx[rh], r);
                    sm[rh] += r;
                }
        } else {
            const int lb = L0 + ta * 128 + wn * 64;
#pragma unroll
            for (int nt = 0; nt < 8; ++nt)
#pragma unroll
                for (int e = 0; e < 4; ++e) {
                    const int rh = e >> 1;
                    const int n  = lb + nt * 8 + kq + (e & 1);
                    const float r = fmaxf(d[nt][e], 0.f);
                    if (n < LOUT) {
                        mx[rh] = fmaxf(mx[rh], r);
                        sm[rh] += r;
                    }
                }
        }
    }

    // ---- lane-group reduce, cross-wn combine, write partials ----
#pragma unroll
    for (int rh = 0; rh < 2; ++rh) {
        float mv = mx[rh], sv = sm[rh];
        mv = fmaxf(mv, __shfl_xor_sync(0xffffffffu, mv, 1));
        sv +=        __shfl_xor_sync(0xffffffffu, sv, 1);
        mv = fmaxf(mv, __shfl_xor_sync(0xffffffffu, mv, 2));
        sv +=        __shfl_xor_sync(0xffffffffu, sv, 2);
        if (tg == 0) {
            const int m = wm * 16 + rh * 8 + grp;
            red[wn * 128 + m]       = mv;
            red[256 + wn * 128 + m] = sv;
        }
    }
    __syncthreads();

    if (tid < 128) {
        const float mv = fmaxf(red[tid], red[128 + tid]);
        const float sv = red[256 + tid] + red[384 + tid];
        float* pp = g_pp + (size_t)(b * 2 + lq) * TWOH;
        pp[hbase + tid]         = mv;
        pp[HNODE + hbase + tid] = sv;      // unscaled sum
    }
}

// ---------------------------------------------------------------------------
// Kernel 2: fused MLP head. 64 CTAs x 512 threads, 4 batches each.
// ---------------------------------------------------------------------------
__global__ void __launch_bounds__(512)
mlp_kernel(const float* __restrict__ wH, const float* __restrict__ wHB,
           const float* __restrict__ wNeu, const float* __restrict__ wNB,
           float* __restrict__ out) {
    __shared__ float4 prow[TWOH];
    __shared__ float  redsm[64];

    const int tid = threadIdx.x;
    const int b0  = blockIdx.x * 4;
    const int o   = tid;

    {
        const int i = tid;
        const float inv = 1.0f / LOUT;
        float4 v;
#pragma unroll
        for (int j = 0; j < 4; ++j) {
            const float* p0 = g_pp + (size_t)((b0 + j) * 2 + 0) * TWOH;
            const float* p1 = g_pp + (size_t)((b0 + j) * 2 + 1) * TWOH;
            ((float*)&v)[j] = (i < HNODE) ? fmaxf(p0[i], p1[i])
                                          : (p0[i] + p1[i]) * inv;
        }
        prow[i] = v;
    }
    __syncthreads();

    float a0 = 0.f, a1 = 0.f, a2 = 0.f, a3 = 0.f;
#pragma unroll 8
    for (int i = 0; i < TWOH; ++i) {
        const float w = wH[i * TWOH + o];
        const float4 p = prow[i];
        a0 = fmaf(p.x, w, a0);
        a1 = fmaf(p.y, w, a1);
        a2 = fmaf(p.z, w, a2);
        a3 = fmaf(p.w, w, a3);
    }

    const float hb = wHB[o];
    const float wv = wNeu[o];
    float vals[4];
    vals[0] = fmaxf(a0 + hb, 0.f) * wv;
    vals[1] = fmaxf(a1 + hb, 0.f) * wv;
    vals[2] = fmaxf(a2 + hb, 0.f) * wv;
    vals[3] = fmaxf(a3 + hb, 0.f) * wv;

    const int lane = tid & 31, wid = tid >> 5;
#pragma unroll
    for (int j = 0; j < 4; ++j) {
        float v = vals[j];
        v += __shfl_xor_sync(0xffffffffu, v, 16);
        v += __shfl_xor_sync(0xffffffffu, v, 8);
        v += __shfl_xor_sync(0xffffffffu, v, 4);
        v += __shfl_xor_sync(0xffffffffu, v, 2);
        v += __shfl_xor_sync(0xffffffffu, v, 1);
        if (lane == 0) redsm[j * 16 + wid] = v;
    }
    __syncthreads();

    if (tid < 4) {
        float s = 0.f;
#pragma unroll
        for (int i = 0; i < 16; ++i) s += redsm[tid * 16 + i];
        out[b0 + tid] = 0.5f * s + wNB[0];
    }
}

// ---------------------------------------------------------------------------
// Launch
// ---------------------------------------------------------------------------
extern "C" void kernel_launch(void* const* d_in, const int* in_sizes, int n_in,
                              void* d_out, int out_size) {
    const float* x     = (const float*)d_in[0];
    const float* wConv = (const float*)d_in[1];
    const float* wRect = (const float*)d_in[2];
    const float* wH    = (const float*)d_in[3];
    const float* wHB   = (const float*)d_in[4];
    const float* wNeu  = (const float*)d_in[5];
    const float* wNB   = (const float*)d_in[6];
    float* out = (float*)d_out;

    prep_kernel<<<4208, 256>>>(x, wConv);
    conv_mma_kernel<<<BATCH * 4, 512>>>(wRect);
    mlp_kernel<<<64, 512>>>(wH, wHB, wNeu, wNB, out);
}